// round 16
// baseline (speedup 1.0000x reference)
#include <cuda_runtime.h>
#include <cstdint>

#define SEQ 8192
#define DIM 64
#define WIN 64
#define QPB 128
#define NTHREADS 512
#define ROWS 256            // staged key rows: QPB + 2*WIN
#define ROWB 144            // smem row stride bytes: 64 halfs + 8 pad halfs

#define KH_OFF 0
#define VH_OFF (KH_OFF + ROWS*ROWB)
#define CB_OFF (VH_OFF + ROWS*ROWB)       // dedicated combine buffer
#define CBS 68                            // combine row stride in floats (272B)
#define SMEM_BYTES (CB_OFF + QPB*CBS*4)   // 73728 + 34816 = 108544

__device__ __forceinline__ uint32_t smem_u32(const void* p) {
    uint32_t a; asm("{ .reg .u64 t; cvta.to.shared.u64 t, %1; cvt.u32.u64 %0, t; }" : "=r"(a) : "l"(p));
    return a;
}
__device__ __forceinline__ float ex2f(float x) { float r; asm("ex2.approx.f32 %0,%1;" : "=f"(r) : "f"(x)); return r; }

// pack {lo: a, hi: b} as f16x2 (round-to-nearest)
__device__ __forceinline__ uint32_t pack_f16x2(float a, float b) {
    uint32_t r; asm("cvt.rn.f16x2.f32 %0,%1,%2;" : "=r"(r) : "f"(b), "f"(a)); return r;
}

__device__ __forceinline__ void ldsm4(uint32_t r[4], uint32_t addr) {
    asm volatile("ldmatrix.sync.aligned.m8n8.x4.shared.b16 {%0,%1,%2,%3}, [%4];"
        : "=r"(r[0]), "=r"(r[1]), "=r"(r[2]), "=r"(r[3]) : "r"(addr));
}
__device__ __forceinline__ void ldsm4t(uint32_t r[4], uint32_t addr) {
    asm volatile("ldmatrix.sync.aligned.m8n8.x4.trans.shared.b16 {%0,%1,%2,%3}, [%4];"
        : "=r"(r[0]), "=r"(r[1]), "=r"(r[2]), "=r"(r[3]) : "r"(addr));
}
__device__ __forceinline__ void mma_f16(float c[4], const uint32_t a[4], uint32_t b0, uint32_t b1) {
    asm volatile("mma.sync.aligned.m16n8k16.row.col.f32.f16.f16.f32 "
        "{%0,%1,%2,%3}, {%4,%5,%6,%7}, {%8,%9}, {%0,%1,%2,%3};"
        : "+f"(c[0]), "+f"(c[1]), "+f"(c[2]), "+f"(c[3])
        : "r"(a[0]), "r"(a[1]), "r"(a[2]), "r"(a[3]), "r"(b0), "r"(b1));
}
#define BAR_PAIR(id) asm volatile("bar.sync %0, 64;" :: "r"(id) : "memory")

// Fused S -> exp -> pack -> PV, one 16-key chunk per iteration.
// Chunk ks covers local keys [lkoff + 16ks, lkoff + 16ks + 16).
template<int NKS>
__device__ __forceinline__ void fused_phase(
    float (*oacc)[4], const uint32_t (*aqh)[4],
    uint32_t kaddr, uint32_t vaddr,
    int lkoff, int cc,
    int lo0, unsigned span0, int lo1, unsigned span1,
    float& rs0, float& rs1)
{
    #pragma unroll
    for (int ks = 0; ks < NKS; ks++) {
        // ---- S for n-tiles 2ks, 2ks+1 (dual accumulator chains) ----
        uint32_t b0[4], b1[4], b2[4], b3[4];
        const uint32_t ka = kaddr + (uint32_t)(2 * ks) * 8 * ROWB;
        ldsm4(b0, ka);                 // tile 2ks, dims 0-31
        ldsm4(b1, ka + 64);            // tile 2ks, dims 32-63
        ldsm4(b2, ka + 8 * ROWB);      // tile 2ks+1, dims 0-31
        ldsm4(b3, ka + 8 * ROWB + 64); // tile 2ks+1, dims 32-63
        float s0[4] = {0.f, 0.f, 0.f, 0.f};
        float s1[4] = {0.f, 0.f, 0.f, 0.f};
        mma_f16(s0, aqh[0], b0[0], b0[1]);
        mma_f16(s1, aqh[0], b2[0], b2[1]);
        mma_f16(s0, aqh[1], b0[2], b0[3]);
        mma_f16(s1, aqh[1], b2[2], b2[3]);
        mma_f16(s0, aqh[2], b1[0], b1[1]);
        mma_f16(s1, aqh[2], b3[0], b3[1]);
        mma_f16(s0, aqh[3], b1[2], b1[3]);
        mma_f16(s1, aqh[3], b3[2], b3[3]);

        // ---- masked exp (log2-domain scores) + row sums ----
        const int klo = lkoff + ks * 16 + cc;
        float p00 = ((unsigned)(klo     - lo0) <= span0) ? ex2f(s0[0]) : 0.f;
        float p01 = ((unsigned)(klo + 1 - lo0) <= span0) ? ex2f(s0[1]) : 0.f;
        float p02 = ((unsigned)(klo     - lo1) <= span1) ? ex2f(s0[2]) : 0.f;
        float p03 = ((unsigned)(klo + 1 - lo1) <= span1) ? ex2f(s0[3]) : 0.f;
        float p10 = ((unsigned)(klo + 8 - lo0) <= span0) ? ex2f(s1[0]) : 0.f;
        float p11 = ((unsigned)(klo + 9 - lo0) <= span0) ? ex2f(s1[1]) : 0.f;
        float p12 = ((unsigned)(klo + 8 - lo1) <= span1) ? ex2f(s1[2]) : 0.f;
        float p13 = ((unsigned)(klo + 9 - lo1) <= span1) ? ex2f(s1[3]) : 0.f;
        rs0 += (p00 + p01) + (p10 + p11);
        rs1 += (p02 + p03) + (p12 + p13);

        // ---- pack P as A-fragment ----
        uint32_t ah[4];
        ah[0] = pack_f16x2(p00, p01);
        ah[1] = pack_f16x2(p02, p03);
        ah[2] = pack_f16x2(p10, p11);
        ah[3] = pack_f16x2(p12, p13);

        // ---- PV for this chunk ----
        const uint32_t va = vaddr + (uint32_t)ks * 16 * ROWB;
        #pragma unroll
        for (int nt0 = 0; nt0 < 8; nt0 += 2) {
            uint32_t bb[4];
            ldsm4t(bb, va + nt0 * 16);
            mma_f16(oacc[nt0],     ah, bb[0], bb[1]);
            mma_f16(oacc[nt0 + 1], ah, bb[2], bb[3]);
        }
    }
}

__global__ void __launch_bounds__(NTHREADS, 1)
swa_hmma_kernel(const float* __restrict__ q, const float* __restrict__ k,
                const float* __restrict__ v, float* __restrict__ out)
{
    extern __shared__ char smem[];
    const uint32_t sb = smem_u32(smem);
    const int t = threadIdx.x;

    const int tilesPerB = SEQ / QPB;
    const int b  = blockIdx.x / tilesPerB;
    const int Q0 = (blockIdx.x % tilesPerB) * QPB;

    const float* qb = q + (size_t)b * SEQ * DIM;
    const float* kb = k + (size_t)b * SEQ * DIM;
    const float* vb = v + (size_t)b * SEQ * DIM;
    float*       ob = out + (size_t)b * SEQ * DIM;

    // ---- stage K/V rows [Q0-64, Q0+192): batched loads, then f16 convert ----
    {
        const int c4 = t & 15;
        const int rb = t >> 4;
        float4 kbuf[8], vbuf[8];
        #pragma unroll
        for (int i = 0; i < 8; i++) {
            int j = Q0 - WIN + rb + 32 * i;
            bool ok = (j >= 0 && j < SEQ);
            const float4* kp = (const float4*)(kb + (size_t)j * DIM) + c4;
            const float4* vp = (const float4*)(vb + (size_t)j * DIM) + c4;
            kbuf[i] = ok ? __ldg(kp) : make_float4(0.f, 0.f, 0.f, 0.f);
            vbuf[i] = ok ? __ldg(vp) : make_float4(0.f, 0.f, 0.f, 0.f);
        }
        #pragma unroll
        for (int i = 0; i < 8; i++) {
            int r = rb + 32 * i;
            *(uint2*)(smem + KH_OFF + r * ROWB + c4 * 8) =
                make_uint2(pack_f16x2(kbuf[i].x, kbuf[i].y), pack_f16x2(kbuf[i].z, kbuf[i].w));
        }
        #pragma unroll
        for (int i = 0; i < 8; i++) {
            int r = rb + 32 * i;
            *(uint2*)(smem + VH_OFF + r * ROWB + c4 * 8) =
                make_uint2(pack_f16x2(vbuf[i].x, vbuf[i].y), pack_f16x2(vbuf[i].z, vbuf[i].w));
        }
    }

    const int w    = t >> 5;
    const int l    = t & 31;
    const int pair = w & 7;        // query group: rows Q0+pair*16 .. +15
    const int h    = w >> 3;       // key-span half: 0 -> lk [0,80), 1 -> lk [80,144)
    const int lkoff = h ? 80 : 0;

    // ---- build Q A-fragments from gmem (prescale + single f16 convert) ----
    // m16n8k16 A mapping: a0=(g, c2), a1=(g+8, c2), a2=(g, c2+8), a3=(g+8, c2+8)
    const float PRE = 0.125f * 1.4426950408889634f;   // 1/sqrt(D) * log2(e)
    uint32_t aqh[4][4];
    {
        const int g  = l >> 2;
        const int c2 = (l & 3) * 2;
        const float* q0 = qb + (size_t)(Q0 + pair * 16 + g) * DIM + c2;
        const float* q1 = q0 + 8 * DIM;
        float2 f0[8], f1[8];
        #pragma unroll
        for (int ks = 0; ks < 4; ks++) {
            #pragma unroll
            for (int half = 0; half < 2; half++) {
                f0[ks * 2 + half] = *(const float2*)(q0 + ks * 16 + half * 8);
                f1[ks * 2 + half] = *(const float2*)(q1 + ks * 16 + half * 8);
            }
        }
        #pragma unroll
        for (int ks = 0; ks < 4; ks++) {
            #pragma unroll
            for (int half = 0; half < 2; half++) {
                float2 a0 = f0[ks * 2 + half], a1 = f1[ks * 2 + half];
                aqh[ks][half * 2]     = pack_f16x2(a0.x * PRE, a0.y * PRE);
                aqh[ks][half * 2 + 1] = pack_f16x2(a1.x * PRE, a1.y * PRE);
            }
        }
    }
    __syncthreads();

    // S-phase lane addressing: lane groups 0-7/8-15/16-23/24-31 -> col chunks 0/16/32/48
    const uint32_t kaddr = sb + KH_OFF
                         + (uint32_t)(pair * 16 + lkoff + (l & 7)) * ROWB
                         + (l >> 3) * 16;
    // PV x4t lanes: g0 rows 0-7 col+0, g1 rows 8-15 col+0, g2 rows 0-7 col+16, g3 rows 8-15 col+16
    const uint32_t vaddr = sb + VH_OFF
                         + (uint32_t)(pair * 16 + lkoff + (l & 7) + ((l >> 3) & 1) * 8) * ROWB
                         + (l >> 4) * 16;

    // per-thread valid key ranges (local key index lk, rows m0 and m0+8)
    const int jbase = Q0 - WIN + pair * 16;
    const int m0 = l >> 2;
    const int cc = (l & 3) * 2;
    const int lo0 = max(m0, -jbase);
    const unsigned span0 = (unsigned)(min(m0 + 2 * WIN, SEQ - 1 - jbase) - lo0);
    const int lo1 = max(m0 + 8, -jbase);
    const unsigned span1 = (unsigned)(min(m0 + 8 + 2 * WIN, SEQ - 1 - jbase) - lo1);

    float rs0 = 0.f, rs1 = 0.f;
    float oacc[8][4];
    #pragma unroll
    for (int nt = 0; nt < 8; nt++)
        #pragma unroll
        for (int i = 0; i < 4; i++) oacc[nt][i] = 0.f;

    if (h == 0)
        fused_phase<5>(oacc, aqh, kaddr, vaddr, 0,  cc, lo0, span0, lo1, span1, rs0, rs1);
    else
        fused_phase<4>(oacc, aqh, kaddr, vaddr, 80, cc, lo0, span0, lo1, span1, rs0, rs1);

    rs0 += __shfl_xor_sync(0xFFFFFFFFu, rs0, 1);
    rs0 += __shfl_xor_sync(0xFFFFFFFFu, rs0, 2);
    rs1 += __shfl_xor_sync(0xFFFFFFFFu, rs1, 1);
    rs1 += __shfl_xor_sync(0xFFFFFFFFu, rs1, 2);

    // ---- combine halves via dedicated smem buffer, per-pair named barrier ----
    float* cb = (float*)(smem + CB_OFF);
    if (h == 1) {
        float* p0 = cb + (size_t)(pair * 16 + m0) * CBS;
        float* p1 = p0 + 8 * CBS;
        #pragma unroll
        for (int nt = 0; nt < 8; nt++) {
            *(float2*)(p0 + nt * 8 + cc) = make_float2(oacc[nt][0], oacc[nt][1]);
            *(float2*)(p1 + nt * 8 + cc) = make_float2(oacc[nt][2], oacc[nt][3]);
        }
        if (cc == 0) { p0[64] = rs0; p1[64] = rs1; }
    }
    BAR_PAIR(pair + 1);            // syncs only the 2 warps of this pair
    if (h == 0) {
        const float* p0 = cb + (size_t)(pair * 16 + m0) * CBS;
        const float* p1 = p0 + 8 * CBS;
        #pragma unroll
        for (int nt = 0; nt < 8; nt++) {
            float2 u0 = *(const float2*)(p0 + nt * 8 + cc);
            float2 u1 = *(const float2*)(p1 + nt * 8 + cc);
            oacc[nt][0] += u0.x; oacc[nt][1] += u0.y;
            oacc[nt][2] += u1.x; oacc[nt][3] += u1.y;
        }
        float inv0 = 1.f / (rs0 + p0[64]);
        float inv1 = 1.f / (rs1 + p1[64]);
        float* orow0 = ob + (size_t)(Q0 + pair * 16 + m0) * DIM;
        float* orow1 = orow0 + 8 * DIM;
        #pragma unroll
        for (int nt = 0; nt < 8; nt++) {
            *(float2*)(orow0 + nt * 8 + cc) = make_float2(oacc[nt][0] * inv0, oacc[nt][1] * inv0);
            *(float2*)(orow1 + nt * 8 + cc) = make_float2(oacc[nt][2] * inv1, oacc[nt][3] * inv1);
        }
    }
}

extern "C" void kernel_launch(void* const* d_in, const int* in_sizes, int n_in,
                              void* d_out, int out_size)
{
    const float* q = (const float*)d_in[0];
    const float* k = (const float*)d_in[1];
    const float* v = (const float*)d_in[2];
    float* out = (float*)d_out;

    int B = in_sizes[0] / (SEQ * DIM);

    cudaFuncSetAttribute(swa_hmma_kernel,
                         cudaFuncAttributeMaxDynamicSharedMemorySize, SMEM_BYTES);

    dim3 grid(B * (SEQ / QPB));
    swa_hmma_kernel<<<grid, NTHREADS, SMEM_BYTES>>>(q, k, v, out);
}